// round 17
// baseline (speedup 1.0000x reference)
#include <cuda_runtime.h>
#include <cstdint>
#include <math_constants.h>

// Sampler: penalties + temperature + top-k/top-p mask + gumbel sample + top-L logprobs.
// One CTA per row.
//
// R17 vs R16: the 1024-thread CTA pinned the kernel at the 63-register ceiling
// (64K RF / 1024 threads), which forbade software pipelining (explains R11's
// regression and the flat 46-74us across all structural rounds). CTA shrinks
// to 512 threads (127 regs available); pass 1 now explicitly double-buffers
// the next chunk's 4 float4 + 2 bitmap words in registers while processing the
// current chunk. Pass 2 uses static round-robin (no atomic queue dependency).
// Gumbel argmax parallelized as an exact (value,index) max-reduce. All
// order-sensitive arithmetic (S accumulation, top-p serial prefix) unchanged.

#define NT       512
#define SHIFT    20
#define HB       4096          // ordered-float bins: ordf(x) >> 20
#define CAND_CAP 2048
#define HASH_SZ  512
#define BM_WORDS 4096          // supports V up to 131072
#define WPT      (BM_WORDS / NT)  // 8
#define MAXCHUNK 256           // V/512 <= 256
#define NSP      5             // specials per thread (512*5 = 2560 >= 2308)
#define NW       (NT / 32)     // 16 warps
#define BIG_NEG  (-1e30f)
#define SAMP_EPS 1e-5f
#define LOG2E    1.4426950408889634f

__device__ __forceinline__ unsigned ordf(float x) {
    unsigned u = __float_as_uint(x);
    return (u & 0x80000000u) ? ~u : (u | 0x80000000u);
}

__device__ __forceinline__ float ex2(float a) {
    float r;
    asm("ex2.approx.f32 %0, %1;" : "=f"(r) : "f"(a));
    return r;                   // ex2(-inf) = 0
}

__device__ __forceinline__ int hlookup(const int* hkey, const int* hcnt, int tok) {
    unsigned slot = ((unsigned)tok * 2654435761u) & (HASH_SZ - 1);
    while (true) {
        int k = hkey[slot];
        if (k == tok) return hcnt[slot];
        if (k == -1)  return 0;
        slot = (slot + 1) & (HASH_SZ - 1);
    }
}

// Full reference-order transform for a special (bitmap-marked) token:
// stop-min (if needed) -> repetition (if prompt/output member) -> freq/presence
// (if output member) -> temperature.
__device__ __forceinline__ float spec_val(float x, int v, bool need,
    int s0, int s1, int s2, int s3, const int* stopPenSh,
    float rp, float fp, float pp, float invt,
    const int* hkey, const int* hcnt)
{
    bool penal = true;
    if (need) {
        int which = (v == s0) ? 0 : (v == s1) ? 1 : (v == s2) ? 2 : (v == s3) ? 3 : -1;
        if (which >= 0) {
            penal = stopPenSh[which] != 0;   // was it in prompt|output?
            x = fminf(x, BIG_NEG);
        }
    }
    if (penal) {
        x = (x > 0.0f) ? (x / rp) : (x * rp);
        int c = hlookup(hkey, hcnt, v);
        if (c > 0) x -= fp * (float)c + pp;
    }
    return x * invt;
}

__global__ __launch_bounds__(NT, 1) void sampler_kernel(
    const float* __restrict__ logits,
    const int*   __restrict__ prompt_ids,
    const int*   __restrict__ output_ids,
    const int*   __restrict__ stop_ids,
    const int*   __restrict__ min_tokens,
    const float* __restrict__ presence,
    const float* __restrict__ frequency,
    const float* __restrict__ repetition,
    const float* __restrict__ temperature,
    const int*   __restrict__ top_k,
    const float* __restrict__ top_p,
    const float* __restrict__ noise,
    float*       __restrict__ out,
    int B, int V, int P, int O, int S, int L)
{
    __shared__ unsigned bm[BM_WORDS];          // 16KB: prompt|output|(stops if need)
    __shared__ int   hkey[HASH_SZ];            // output-token count hash (4KB)
    __shared__ int   hcnt[HASH_SZ];
    __shared__ int   scratch[HB];              // 16KB overlay: hist/specials-list -> cand
    int*   hist  = scratch;
    float* candV = reinterpret_cast<float*>(scratch);
    int*   candI = scratch + CAND_CAP;
    __shared__ float chunkMax[MAXCHUNK];       // 1KB (512-elem chunks, x-domain)
    __shared__ int   flagged[MAXCHUNK];        // 1KB

    __shared__ float sortedV[64];
    __shared__ int   sortedI[64];
    __shared__ float scoreV[64];
    __shared__ float eV[64];
    __shared__ float redf[NW];
    __shared__ int   redi[NW];
    __shared__ float bestS[2];
    __shared__ int   bestI[2];
    __shared__ int   seg[HB / 32];             // 128 segment sums for theta scan
    __shared__ int   stopPenSh[4];
    __shared__ int   shCand, shNkept, shNFlag, shNSpec;
    __shared__ float shS, shLse, shTheta;

    const int b    = blockIdx.x;
    const int tid  = threadIdx.x;
    const int lane = tid & 31;
    const int wid  = tid >> 5;
    const int nChunk = V >> 9;                 // 512-elem chunks (V multiple of 512)

    // ---- init shared ----
    for (int i = tid; i < BM_WORDS; i += NT) bm[i] = 0u;
    for (int i = tid; i < HB;       i += NT) hist[i] = 0;
    for (int i = tid; i < HASH_SZ;  i += NT) { hkey[i] = -1; hcnt[i] = 0; }
    if (tid == 0) { shCand = 0; shNFlag = 0; }
    __syncthreads();

    // ---- row params ----
    const bool  need = min_tokens[b] > O;
    const float rp = repetition[b], fp = frequency[b], pp = presence[b];
    const float traw = temperature[b];
    const float t = (traw < SAMP_EPS) ? 1.0f : traw;
    const float invt = 1.0f / t;
    const float cE = invt * LOG2E;             // fused exp2 argument scale
    const int s0 = (S > 0) ? stop_ids[(size_t)b * S + 0] : -1;
    const int s1 = (S > 1) ? stop_ids[(size_t)b * S + 1] : -1;
    const int s2 = (S > 2) ? stop_ids[(size_t)b * S + 2] : -1;
    const int s3 = (S > 3) ? stop_ids[(size_t)b * S + 3] : -1;

    // ---- build membership bitmap + output counts ----
    for (int i = tid; i < O; i += NT) {
        int tok = output_ids[(size_t)b * O + i];
        atomicOr(&bm[tok >> 5], 1u << (tok & 31));
        unsigned slot = ((unsigned)tok * 2654435761u) & (HASH_SZ - 1);
        while (true) {
            int old = atomicCAS(&hkey[slot], -1, tok);
            if (old == -1 || old == tok) { atomicAdd(&hcnt[slot], 1); break; }
            slot = (slot + 1) & (HASH_SZ - 1);
        }
    }
    for (int i = tid; i < P; i += NT) {
        int tok = prompt_ids[(size_t)b * P + i];
        atomicOr(&bm[tok >> 5], 1u << (tok & 31));
    }
    __syncthreads();

    // ---- fold stop tokens into bitmap (recording prior membership) ----
    if (tid == 0 && need) {
        int ss[4] = {s0, s1, s2, s3};
        int pen[4];
        #pragma unroll
        for (int k = 0; k < 4; k++)
            pen[k] = (ss[k] >= 0) ? (int)((bm[ss[k] >> 5] >> (ss[k] & 31)) & 1u) : 0;
        #pragma unroll
        for (int k = 0; k < 4; k++) {
            stopPenSh[k] = pen[k];
            if (ss[k] >= 0) bm[ss[k] >> 5] |= 1u << (ss[k] & 31);
        }
    }
    __syncthreads();

    // ===== compact specials (deterministic prefix order) into hist region =====
    int tc = 0;
    {
        #pragma unroll
        for (int k = 0; k < WPT; k++) tc += __popc(bm[tid * WPT + k]);
    }
    int incl = tc;
    #pragma unroll
    for (int o = 1; o < 32; o <<= 1) {
        int nv = __shfl_up_sync(0xffffffffu, incl, o);
        if (lane >= o) incl += nv;
    }
    if (lane == 31) redi[wid] = incl;
    __syncthreads();
    if (wid == 0) {
        int v = (lane < NW) ? redi[lane] : 0;
        int wincl = v;
        #pragma unroll
        for (int o = 1; o < 32; o <<= 1) {
            int nv = __shfl_up_sync(0xffffffffu, wincl, o);
            if (lane >= o) wincl += nv;
        }
        if (lane < NW) redi[lane] = wincl - v;       // exclusive warp base
        if (lane == NW - 1) shNSpec = wincl;         // block total
    }
    __syncthreads();
    {
        int pos = redi[wid] + incl - tc;             // exclusive prefix for this thread
        #pragma unroll
        for (int k = 0; k < WPT; k++) {
            unsigned w = bm[tid * WPT + k];
            int baseTok = (tid * WPT + k) << 5;
            while (w) {
                int bpos = __ffs(w) - 1; w &= (w - 1);
                hist[pos++] = baseTok + bpos;        // temp list in hist region
            }
        }
    }
    __syncthreads();
    const int nSpec = shNSpec;                       // <= P+O+4 <= 2308 < NSP*NT

    // each thread takes its <=NSP specials into registers
    int sv[NSP];
    int myN = 0;
    #pragma unroll
    for (int j = 0; j < NSP; j++) {
        int i = tid + j * NT;
        sv[j] = (i < nSpec) ? hist[i] : 0;
        if (i < nSpec) myN = j + 1;
    }
    __syncthreads();
    for (int i = tid; i < nSpec; i += NT) hist[i] = 0;   // re-zero used region
    __syncthreads();

    const float* lrow = logits + (size_t)b * V;

    // ===== specials phase A: batched independent loads, compute once =====
    float sx[NSP];
    float mx = -CUDART_INF_F;                   // thread max, x-domain
    float s  = 0.0f;
    {
        float sraw[NSP];
        #pragma unroll
        for (int j = 0; j < NSP; j++)
            sraw[j] = (j < myN) ? __ldg(lrow + sv[j]) : 0.0f;
        #pragma unroll
        for (int j = 0; j < NSP; j++) {
            if (j < myN) {
                sx[j] = spec_val(sraw[j], sv[j], need, s0, s1, s2, s3, stopPenSh,
                                 rp, fp, pp, invt, hkey, hcnt);
                mx = fmaxf(mx, sx[j]);
                s += __expf(sx[j]);
            } else sx[j] = -CUDART_INF_F;
        }
    }

    // ===== PASS 1: software-pipelined stream (prefetch next chunk into regs) =====
    float mxr = -CUDART_INF_F;                  // thread max over main tokens, RAW
    {
        int chunk = wid;                        // 16 warps round-robin
        bool valid = (chunk << 9) < V;
        float4 a0, a1, a2, a3; unsigned wA = 0, wB = 0;
        if (valid) {
            const int b0 = (chunk << 9) + (lane << 3);
            a0 = *reinterpret_cast<const float4*>(lrow + b0);
            a1 = *reinterpret_cast<const float4*>(lrow + b0 + 4);
            a2 = *reinterpret_cast<const float4*>(lrow + b0 + 256);
            a3 = *reinterpret_cast<const float4*>(lrow + b0 + 260);
            wA = bm[b0 >> 5] >> (b0 & 31);
            wB = bm[(b0 + 256) >> 5] >> (b0 & 31);
        }
        while (valid) {
            const int nchk = chunk + NW;
            const bool nvalid = (nchk << 9) < V;
            float4 c0, c1, c2, c3; unsigned nwA = 0, nwB = 0;
            if (nvalid) {                        // prefetch next chunk
                const int b1 = (nchk << 9) + (lane << 3);
                c0 = *reinterpret_cast<const float4*>(lrow + b1);
                c1 = *reinterpret_cast<const float4*>(lrow + b1 + 4);
                c2 = *reinterpret_cast<const float4*>(lrow + b1 + 256);
                c3 = *reinterpret_cast<const float4*>(lrow + b1 + 260);
                nwA = bm[b1 >> 5] >> (b1 & 31);
                nwB = bm[(b1 + 256) >> 5] >> (b1 & 31);
            }
            // ---- process current chunk ----
            float imr = -CUDART_INF_F;
            {
                float r0 = (wA &   1u) ? -CUDART_INF_F : a0.x;
                float r1 = (wA &   2u) ? -CUDART_INF_F : a0.y;
                float r2 = (wA &   4u) ? -CUDART_INF_F : a0.z;
                float r3 = (wA &   8u) ? -CUDART_INF_F : a0.w;
                float r4 = (wA &  16u) ? -CUDART_INF_F : a1.x;
                float r5 = (wA &  32u) ? -CUDART_INF_F : a1.y;
                float r6 = (wA &  64u) ? -CUDART_INF_F : a1.z;
                float r7 = (wA & 128u) ? -CUDART_INF_F : a1.w;
                float e01 = ex2(r0 * cE) + ex2(r1 * cE);
                float e23 = ex2(r2 * cE) + ex2(r3 * cE);
                float e45 = ex2(r4 * cE) + ex2(r5 * cE);
                float e67 = ex2(r6 * cE) + ex2(r7 * cE);
                s += (e01 + e23) + (e45 + e67);
                imr = fmaxf(fmaxf(fmaxf(r0, r1), fmaxf(r2, r3)),
                            fmaxf(fmaxf(r4, r5), fmaxf(r6, r7)));
            }
            {
                float r0 = (wB &   1u) ? -CUDART_INF_F : a2.x;
                float r1 = (wB &   2u) ? -CUDART_INF_F : a2.y;
                float r2 = (wB &   4u) ? -CUDART_INF_F : a2.z;
                float r3 = (wB &   8u) ? -CUDART_INF_F : a2.w;
                float r4 = (wB &  16u) ? -CUDART_INF_F : a3.x;
                float r5 = (wB &  32u) ? -CUDART_INF_F : a3.y;
                float r6 = (wB &  64u) ? -CUDART_INF_F : a3.z;
                float r7 = (wB & 128u) ? -CUDART_INF_F : a3.w;
                float e01 = ex2(r0 * cE) + ex2(r1 * cE);
                float e23 = ex2(r2 * cE) + ex2(r3 * cE);
                float e45 = ex2(r4 * cE) + ex2(r5 * cE);
                float e67 = ex2(r6 * cE) + ex2(r7 * cE);
                s += (e01 + e23) + (e45 + e67);
                float im2 = fmaxf(fmaxf(fmaxf(r0, r1), fmaxf(r2, r3)),
                                  fmaxf(fmaxf(r4, r5), fmaxf(r6, r7)));
                imr = fmaxf(imr, im2);
            }
            mxr = fmaxf(mxr, imr);
            float cm = imr;
            #pragma unroll
            for (int o = 16; o; o >>= 1) cm = fmaxf(cm, __shfl_xor_sync(0xffffffffu, cm, o));
            if (lane == 0) chunkMax[chunk] = cm * invt;   // x-domain (max commutes)
            // ---- rotate ----
            chunk = nchk; valid = nvalid;
            a0 = c0; a1 = c1; a2 = c2; a3 = c3; wA = nwA; wB = nwB;
        }
    }
    mx = fmaxf(mx, mxr * invt);                 // thread max, x-domain

    // histogram of the 512 thread-maxes (x-domain); warp partial sums
    atomicAdd(&hist[ordf(mx) >> SHIFT], 1);
    float ws = s;
    #pragma unroll
    for (int o = 16; o; o >>= 1) ws += __shfl_xor_sync(0xffffffffu, ws, o);
    if (lane == 0) redf[wid] = ws;
    __syncthreads();                                 // hist + redf + chunkMax complete

    // ---- theta: parallel segment sums, then 2-level scan in warp 0 ----
    if (tid < HB / 32) {                             // 128 threads: 32-bin segment sums
        int sum = 0;
        const int base = tid << 5;
        #pragma unroll
        for (int k = 0; k < 32; k++) sum += hist[base + k];
        seg[tid] = sum;
    }
    if (wid == NW - 1 && lane == 0) {                // final exp-sum (fixed order)
        float v = 0.0f;
        #pragma unroll
        for (int i = 0; i < NW; i++) v += redf[i];
        shS = v;
    }
    __syncthreads();
    if (wid == 0) {                                  // crossing: cum-from-top >= 64
        int running = 0;
        int done = 0;
        for (int cb = (HB / 32 / 32) - 1; cb >= 0 && !done; cb--) {
            int sidx = (cb << 5) + (31 - lane);      // lane 0 = highest segment
            int cnt = seg[sidx];
            int pref = cnt;
            #pragma unroll
            for (int o = 1; o < 32; o <<= 1) {
                int nv = __shfl_up_sync(0xffffffffu, pref, o);
                if (lane >= o) pref += nv;
            }
            int tot = __shfl_sync(0xffffffffu, pref, 31);
            if (running + tot >= 64) {
                unsigned msk = __ballot_sync(0xffffffffu, running + pref >= 64);
                int Lm = __ffs(msk) - 1;
                int prefL = __shfl_sync(0xffffffffu, pref, Lm);
                int cntL  = __shfl_sync(0xffffffffu, cnt,  Lm);
                int sstar = (cb << 5) + (31 - Lm);
                int baseCnt = running + prefL - cntL;    // count strictly above segment
                int bin = (sstar << 5) + (31 - lane);    // lane 0 = highest bin
                int c2 = hist[bin];
                int p2 = c2;
                #pragma unroll
                for (int o = 1; o < 32; o <<= 1) {
                    int nv = __shfl_up_sync(0xffffffffu, p2, o);
                    if (lane >= o) p2 += nv;
                }
                unsigned msk2 = __ballot_sync(0xffffffffu, baseCnt + p2 >= 64);
                int Lm2 = __ffs(msk2) - 1;
                int bstar = (sstar << 5) + (31 - Lm2);
                if (bstar < 0) bstar = 0;
                if (lane == 0) {
                    unsigned tu = (unsigned)bstar << SHIFT;   // bin lower edge
                    float th;
                    if (tu == 0u)               th = -CUDART_INF_F;
                    else if (tu & 0x80000000u)  th = __uint_as_float(tu ^ 0x80000000u);
                    else                        th = __uint_as_float(~tu);
                    shTheta = th;
                }
                done = 1;
            }
            running += tot;
        }
    }
    __syncthreads();
    const float theta = shTheta;

    // ---- flag 512-elem chunks that can contain a candidate ----
    if (tid < nChunk && chunkMax[tid] >= theta) {
        int p = atomicAdd(&shNFlag, 1);
        flagged[p] = tid;
    }
    __syncthreads();
    const int nFlag = shNFlag;

    // ===== PASS 2: candidates only, flagged chunks, static round-robin =====
    for (int mc = wid; mc < nFlag; mc += NW) {
        const int c = flagged[mc];
        #pragma unroll
        for (int half = 0; half < 2; half++) {
            const int base = (c << 9) + (half << 8) + (lane << 3);
            const float4 q0 = *reinterpret_cast<const float4*>(lrow + base);
            const float4 q1 = *reinterpret_cast<const float4*>(lrow + base + 4);
            const unsigned w = bm[base >> 5] >> (base & 31);

            float x;
            #define CAND_TEST(BIT, VAL, OFF)                                   \
                if (!(w & BIT)) {                                              \
                    x = (VAL) * invt;                                          \
                    if (x >= theta) {                                          \
                        int p = atomicAdd(&shCand, 1);                         \
                        if (p < CAND_CAP) { candV[p] = x; candI[p] = base + OFF; } \
                    }                                                          \
                }
            CAND_TEST(  1u, q0.x, 0)
            CAND_TEST(  2u, q0.y, 1)
            CAND_TEST(  4u, q0.z, 2)
            CAND_TEST(  8u, q0.w, 3)
            CAND_TEST( 16u, q1.x, 4)
            CAND_TEST( 32u, q1.y, 5)
            CAND_TEST( 64u, q1.z, 6)
            CAND_TEST(128u, q1.w, 7)
            #undef CAND_TEST
        }
    }
    // specials phase B: candidate test straight from registers (no loads)
    #pragma unroll
    for (int j = 0; j < NSP; j++) {
        if (j < myN && sx[j] >= theta) {
            int p = atomicAdd(&shCand, 1);
            if (p < CAND_CAP) { candV[p] = sx[j]; candI[p] = sv[j]; }
        }
    }
    __syncthreads();

    // ---- exact rank sort of candidates (value desc, index asc; stable) ----
    const int C = min(shCand, CAND_CAP);
    const int Ntop = min(64, C);
    for (int i = tid; i < C; i += NT) {
        float vi = candV[i]; int ii = candI[i];
        int r = 0;
        for (int j = 0; j < C; j++) {
            float vj = candV[j];
            if (vj > vi || (vj == vi && candI[j] < ii)) r++;
        }
        if (r < 64) { sortedV[r] = vi; sortedI[r] = ii; }
    }
    __syncthreads();

    // parallel exp of top-64 (keeps expf out of the serial chain)
    if (tid < 64) eV[tid] = (tid < Ntop) ? expf(sortedV[tid]) : 0.0f;
    __syncthreads();

    // ---- prefix top-k & top-p (exclusive cumsum, strict <), masked LSE ----
    // (kept serial: accumulation order is semantics)
    if (tid == 0) {
        const float Sall = shS;
        int ke = top_k[b]; if (ke < 1) ke = V;
        const float tp = top_p[b];
        float c = 0.0f; int nk = 0;
        for (int i = 0; i < Ntop; i++) {
            if (i < ke && c < tp) { nk = i + 1; c += eV[i] / Sall; }
            else break;
        }
        float sum = 0.0f;
        for (int i = 0; i < nk; i++) sum += eV[i];
        shLse = logf(sum);
        shNkept = nk;
    }
    __syncthreads();
    const int nk = shNkept;
    const float lse = shLse;

    // ---- gumbel scores over kept set (parallel noise gather) ----
    if (tid < 64) {
        if (tid < nk) {
            int idx = sortedI[tid];
            float u = noise[(size_t)b * V + idx];
            float g = -logf(-logf(u));
            scoreV[tid] = sortedV[tid] * invt + g;
        } else scoreV[tid] = -CUDART_INF_F;
    }
    __syncthreads();
    // exact two-warp (score, index) max-reduce; tie -> lower index
    if (tid < 64) {
        float sc = scoreV[tid];
        int   ix = (tid < nk) ? sortedI[tid] : 0x7FFFFFFF;
        #pragma unroll
        for (int o = 16; o; o >>= 1) {
            float osc = __shfl_xor_sync(0xffffffffu, sc, o);
            int   oix = __shfl_xor_sync(0xffffffffu, ix, o);
            if (osc > sc || (osc == sc && oix < ix)) { sc = osc; ix = oix; }
        }
        if (lane == 0) { bestS[tid >> 5] = sc; bestI[tid >> 5] = ix; }
    }
    __syncthreads();
    if (tid == 0) {
        int best;
        if (traw < SAMP_EPS) {
            best = sortedI[0];                       // greedy: ties -> lowest index
        } else {
            float s0_ = bestS[0], s1_ = bestS[1];
            int   i0_ = bestI[0], i1_ = bestI[1];
            best = (s1_ > s0_ || (s1_ == s0_ && i1_ < i0_)) ? i1_ : i0_;
        }
        out[b] = (float)best;
    }

    // ---- top-L logprobs + indices ----
    float* lpOut = out + B + (size_t)b * L;
    float* ixOut = out + B + (size_t)B * L + (size_t)b * L;
    if (tid < L) {
        if (tid < nk) {
            lpOut[tid] = sortedV[tid] - lse;
            ixOut[tid] = (float)sortedI[tid];
        } else {
            lpOut[tid] = BIG_NEG;                    // exact: -1e30 - lse == -1e30 in f32
        }
    }
    // fill remaining index slots with the smallest non-kept token ids
    // (lax.top_k tie-break: ascending index among equal BIG_NEG values)
    const int needFill = L - nk;
    if (needFill > 0 && tid < 192) {
        int cid = tid;
        bool inKept = false; int less = 0;
        for (int i = 0; i < nk; i++) {
            int si = sortedI[i];
            inKept |= (si == cid);
            less += (si < cid);
        }
        if (!inKept) {
            int rank = cid - less;                   // rank among non-kept ids
            if (rank < needFill) ixOut[nk + rank] = (float)cid;
        }
    }
}

extern "C" void kernel_launch(void* const* d_in, const int* in_sizes, int n_in,
                              void* d_out, int out_size) {
    const float* logits  = (const float*)d_in[0];
    const int*   prompt  = (const int*)  d_in[1];
    const int*   outtok  = (const int*)  d_in[2];
    const int*   stoptok = (const int*)  d_in[3];
    const int*   mintok  = (const int*)  d_in[4];
    const float* pres    = (const float*)d_in[5];
    const float* freq    = (const float*)d_in[6];
    const float* rep     = (const float*)d_in[7];
    const float* temp    = (const float*)d_in[8];
    const int*   topk    = (const int*)  d_in[9];
    const float* topp    = (const float*)d_in[10];
    const float* noise   = (const float*)d_in[11];

    const int B = in_sizes[4];
    const int V = in_sizes[0] / B;
    const int P = in_sizes[1] / B;
    const int O = in_sizes[2] / B;
    const int S = in_sizes[3] / B;
    const int L = (out_size / B - 1) / 2;   // [sampled(B), logprobs(B,L), indices(B,L)]

    sampler_kernel<<<B, NT>>>(logits, prompt, outtok, stoptok, mintok,
                              pres, freq, rep, temp, topk, topp, noise,
                              (float*)d_out, B, V, P, O, S, L);
}